// round 1
// baseline (speedup 1.0000x reference)
#include <cuda_runtime.h>
#include <cstdint>

#define NB   2048      // batch B
#define NU   8192      // unique U
#define ND   256       // dim D
#define NR   8         // relations R
#define KTOT (NR*ND + ND)   // 2304 combined GEMM K

// ---------------- scratch (no allocations allowed) ----------------
__device__ __align__(16) float g_neigh[NU * ND];        // 8 MB   gathered E[unique_idx]
__device__ __align__(16) float g_A[(size_t)NB * KTOT];  // 18.9MB [agg(B,R*D) | self emb(B,D)]
__device__ __align__(16) float g_W[KTOT * ND];          // 2.36MB [rel_weights perm | weight^T]

// ---------------- K1a: build combined weight matrix ----------------
// g_W[k][o]: k<R*D -> rel_weights[r][o][d] (r=k/256,d=k%256); else weight[o][k-2048]
__global__ void build_w_kernel(const float* __restrict__ weight,
                               const float* __restrict__ relw) {
    int k = blockIdx.x;
    int o = threadIdx.x;
    float v;
    if (k < NR * ND) {
        int r = k >> 8;
        int d = k & 255;
        v = relw[((size_t)r * ND + o) * ND + d];
    } else {
        int d = k - NR * ND;
        v = weight[o * ND + d];
    }
    g_W[(size_t)k * ND + o] = v;
}

// ---------------- K1b: gathers ----------------
// blocks [0,U): g_neigh[u] = emb[unique_idx[u]]
// blocks [U,U+B): g_A[b][2048+d] = emb[nodes[b]][d]
__global__ void gather_kernel(const float* __restrict__ emb,
                              const int* __restrict__ unique_idx,
                              const int* __restrict__ nodes) {
    int blk = blockIdx.x;
    int t = threadIdx.x;
    if (blk < NU) {
        int src = unique_idx[blk];
        g_neigh[(size_t)blk * ND + t] = emb[(size_t)src * ND + t];
    } else {
        int b = blk - NU;
        int src = nodes[b];
        g_A[(size_t)b * KTOT + NR * ND + t] = emb[(size_t)src * ND + t];
    }
}

// ---------------- K2: mask scan + sparse mean aggregation ----------------
// One block per (r,b) row of masks [R,B,U]. Stream 32KB, collect nonzero u's,
// sort (deterministic order), accumulate neigh rows, normalize by 1/(cnt+eps).
#define LIST_CAP 1024
__global__ void mask_agg_kernel(const float* __restrict__ masks) {
    __shared__ int s_list[LIST_CAP];
    __shared__ int s_cnt;
    int t = threadIdx.x;            // 256 threads, t == output dim d
    int rb = blockIdx.x;            // rb = r*2048 + b, matches masks layout
    int r = rb >> 11;
    int b = rb & 2047;

    if (t == 0) s_cnt = 0;
    __syncthreads();

    const float4* row = (const float4*)(masks + (size_t)rb * NU);
#pragma unroll
    for (int c = 0; c < 8; c++) {
        int f4 = c * 256 + t;       // float4 index within 2048
        float4 v = row[f4];
        int base = f4 * 4;
        if (v.x != 0.0f) { int p = atomicAdd(&s_cnt, 1); if (p < LIST_CAP) s_list[p] = base; }
        if (v.y != 0.0f) { int p = atomicAdd(&s_cnt, 1); if (p < LIST_CAP) s_list[p] = base + 1; }
        if (v.z != 0.0f) { int p = atomicAdd(&s_cnt, 1); if (p < LIST_CAP) s_list[p] = base + 2; }
        if (v.w != 0.0f) { int p = atomicAdd(&s_cnt, 1); if (p < LIST_CAP) s_list[p] = base + 3; }
    }
    __syncthreads();

    int cnt = s_cnt;
    int n = cnt < LIST_CAP ? cnt : LIST_CAP;

    // insertion sort by thread 0 -> deterministic accumulation order (n ~ 10)
    if (t == 0) {
        for (int i = 1; i < n; i++) {
            int key = s_list[i];
            int j = i - 1;
            while (j >= 0 && s_list[j] > key) { s_list[j + 1] = s_list[j]; j--; }
            s_list[j + 1] = key;
        }
    }
    __syncthreads();

    float acc = 0.0f;
    for (int i = 0; i < n; i++) {
        int u = s_list[i];
        acc += g_neigh[(size_t)u * ND + t];
    }
    float norm = 1.0f / ((float)cnt + 1e-10f);
    g_A[(size_t)b * KTOT + r * ND + t] = acc * norm;
}

// ---------------- K3: fused GEMM + ReLU ----------------
// out[b][o] = relu( sum_k A[b][k] * W[k][o] ),  M=2048, N=256, K=2304
// BM=64, BN=32, BK=16, 128 threads, thread tile 4x4, f32x2 packed FMA.
#define BM 64
#define BN 32
#define BK 16

__device__ __forceinline__ unsigned long long pack2(float lo, float hi) {
    unsigned long long v;
    asm("mov.b64 %0, {%1, %2};" : "=l"(v) : "r"(__float_as_uint(lo)), "r"(__float_as_uint(hi)));
    return v;
}
__device__ __forceinline__ void unpack2(unsigned long long v, float& lo, float& hi) {
    unsigned int a, b;
    asm("mov.b64 {%0, %1}, %2;" : "=r"(a), "=r"(b) : "l"(v));
    lo = __uint_as_float(a); hi = __uint_as_float(b);
}
__device__ __forceinline__ unsigned long long fma2(unsigned long long a,
                                                   unsigned long long b,
                                                   unsigned long long c) {
    unsigned long long d;
    asm("fma.rn.f32x2 %0, %1, %2, %3;" : "=l"(d) : "l"(a), "l"(b), "l"(c));
    return d;
}

__global__ __launch_bounds__(128) void gemm_relu_kernel(float* __restrict__ out) {
    __shared__ float As[BK][68];   // [k][m], padded stride (float4-aligned)
    __shared__ float Bs[BK][BN];   // [k][n]

    int tid = threadIdx.x;
    int m0 = blockIdx.x * BM;
    int n0 = blockIdx.y * BN;
    int tx = tid & 7;              // n-dir (8 * 4 = 32)
    int ty = tid >> 3;             // m-dir (16 * 4 = 64)
    int tm = ty * 4, tn = tx * 4;

    unsigned long long acc[4][2];
#pragma unroll
    for (int i = 0; i < 4; i++) { acc[i][0] = 0ULL; acc[i][1] = 0ULL; }

    for (int k0 = 0; k0 < KTOT; k0 += BK) {
        // stage A tile: 64x16 = 256 float4, 2 per thread, store transposed
#pragma unroll
        for (int p = 0; p < 2; p++) {
            int f = tid + p * 128;
            int row = f >> 2;
            int c4 = f & 3;
            float4 av = *(const float4*)&g_A[(size_t)(m0 + row) * KTOT + k0 + c4 * 4];
            As[c4 * 4 + 0][row] = av.x;
            As[c4 * 4 + 1][row] = av.y;
            As[c4 * 4 + 2][row] = av.z;
            As[c4 * 4 + 3][row] = av.w;
        }
        // stage B tile: 16x32 = 128 float4, 1 per thread
        {
            int krow = tid >> 3;
            int c = (tid & 7) * 4;
            float4 bv = *(const float4*)&g_W[(size_t)(k0 + krow) * ND + n0 + c];
            *(float4*)&Bs[krow][c] = bv;
        }
        __syncthreads();

#pragma unroll
        for (int k = 0; k < BK; k++) {
            float4 a = *(const float4*)&As[k][tm];
            const unsigned long long* bp = (const unsigned long long*)&Bs[k][tn];
            unsigned long long b0 = bp[0];
            unsigned long long b1 = bp[1];
            unsigned long long aa0 = pack2(a.x, a.x);
            unsigned long long aa1 = pack2(a.y, a.y);
            unsigned long long aa2 = pack2(a.z, a.z);
            unsigned long long aa3 = pack2(a.w, a.w);
            acc[0][0] = fma2(aa0, b0, acc[0][0]);
            acc[0][1] = fma2(aa0, b1, acc[0][1]);
            acc[1][0] = fma2(aa1, b0, acc[1][0]);
            acc[1][1] = fma2(aa1, b1, acc[1][1]);
            acc[2][0] = fma2(aa2, b0, acc[2][0]);
            acc[2][1] = fma2(aa2, b1, acc[2][1]);
            acc[3][0] = fma2(aa3, b0, acc[3][0]);
            acc[3][1] = fma2(aa3, b1, acc[3][1]);
        }
        __syncthreads();
    }

    // epilogue: ReLU + float4 stores
#pragma unroll
    for (int i = 0; i < 4; i++) {
        float c0, c1, c2, c3;
        unpack2(acc[i][0], c0, c1);
        unpack2(acc[i][1], c2, c3);
        float4 v;
        v.x = c0 > 0.0f ? c0 : 0.0f;
        v.y = c1 > 0.0f ? c1 : 0.0f;
        v.z = c2 > 0.0f ? c2 : 0.0f;
        v.w = c3 > 0.0f ? c3 : 0.0f;
        *(float4*)&out[(size_t)(m0 + tm + i) * ND + n0 + tn] = v;
    }
}

// ---------------- launch ----------------
extern "C" void kernel_launch(void* const* d_in, const int* in_sizes, int n_in,
                              void* d_out, int out_size) {
    const int*   nodes   = nullptr;
    const int*   uniq    = nullptr;
    const float* masks   = nullptr;
    const float* emb     = nullptr;
    const float* weight  = nullptr;
    const float* relw    = nullptr;

    for (int i = 0; i < n_in; i++) {
        switch (in_sizes[i]) {
            case NB:                 nodes  = (const int*)d_in[i];   break; // 2048
            case NU:                 uniq   = (const int*)d_in[i];   break; // 8192
            case NR * NB * NU:       masks  = (const float*)d_in[i]; break; // 134217728
            case 100000 * ND:        emb    = (const float*)d_in[i]; break; // 25600000
            case ND * ND:            weight = (const float*)d_in[i]; break; // 65536
            case NR * ND * ND:       relw   = (const float*)d_in[i]; break; // 524288
            default: break;
        }
    }
    float* out = (float*)d_out;

    build_w_kernel<<<KTOT, 256>>>(weight, relw);
    gather_kernel<<<NU + NB, 256>>>(emb, uniq, nodes);
    mask_agg_kernel<<<NR * NB, 256>>>(masks);
    dim3 g3(NB / BM, ND / BN);
    gemm_relu_kernel<<<g3, 128>>>(out);
}

// round 2
// speedup vs baseline: 1.4116x; 1.4116x over previous
#include <cuda_runtime.h>
#include <cstdint>

#define NB   2048      // batch B
#define NU   8192      // unique U
#define ND   256       // dim D
#define NR   8         // relations R
#define KTOT (NR*ND + ND)   // 2304 combined GEMM K

// ---------------- scratch (no allocations allowed) ----------------
__device__ __align__(16) float g_neigh[NU * ND];         // 8 MB
__device__ __align__(16) float g_A[(size_t)NB * KTOT];   // 18.9 MB
__device__ __align__(16) float g_W[KTOT * ND];           // 2.36 MB

#define SPLIT 9
#define KSPL  (KTOT / SPLIT)   // 256
#define BKK   16
#define ITERS (KSPL / BKK)     // 16
#define BM    128
#define BN    128

__device__ __align__(16) float g_part[(size_t)SPLIT * NB * ND]; // 18 MB

// ---------------- K1a: build combined weight matrix ----------------
__global__ void build_w_kernel(const float* __restrict__ weight,
                               const float* __restrict__ relw) {
    int k = blockIdx.x;
    int o = threadIdx.x;
    float v;
    if (k < NR * ND) {
        int r = k >> 8;
        int d = k & 255;
        v = relw[((size_t)r * ND + o) * ND + d];
    } else {
        int d = k - NR * ND;
        v = weight[o * ND + d];
    }
    g_W[(size_t)k * ND + o] = v;
}

// ---------------- K1b: gathers ----------------
__global__ void gather_kernel(const float* __restrict__ emb,
                              const int* __restrict__ unique_idx,
                              const int* __restrict__ nodes) {
    int blk = blockIdx.x;
    int t = threadIdx.x;
    if (blk < NU) {
        int src = unique_idx[blk];
        g_neigh[(size_t)blk * ND + t] = emb[(size_t)src * ND + t];
    } else {
        int b = blk - NU;
        int src = nodes[b];
        g_A[(size_t)b * KTOT + NR * ND + t] = emb[(size_t)src * ND + t];
    }
}

// ---------------- K2: mask scan + sparse mean aggregation ----------------
#define LIST_CAP 1024
__global__ void mask_agg_kernel(const float* __restrict__ masks) {
    __shared__ int s_list[LIST_CAP];
    __shared__ int s_cnt;
    int t = threadIdx.x;            // 256 threads, t == output dim d
    int rb = blockIdx.x;            // rb = r*2048 + b
    int r = rb >> 11;
    int b = rb & 2047;

    if (t == 0) s_cnt = 0;
    __syncthreads();

    const float4* row = (const float4*)(masks + (size_t)rb * NU);
#pragma unroll
    for (int c = 0; c < 8; c++) {
        int f4 = c * 256 + t;
        float4 v = row[f4];
        int base = f4 * 4;
        if (v.x != 0.0f) { int p = atomicAdd(&s_cnt, 1); if (p < LIST_CAP) s_list[p] = base; }
        if (v.y != 0.0f) { int p = atomicAdd(&s_cnt, 1); if (p < LIST_CAP) s_list[p] = base + 1; }
        if (v.z != 0.0f) { int p = atomicAdd(&s_cnt, 1); if (p < LIST_CAP) s_list[p] = base + 2; }
        if (v.w != 0.0f) { int p = atomicAdd(&s_cnt, 1); if (p < LIST_CAP) s_list[p] = base + 3; }
    }
    __syncthreads();

    int cnt = s_cnt;
    int n = cnt < LIST_CAP ? cnt : LIST_CAP;

    if (t == 0) {   // deterministic order
        for (int i = 1; i < n; i++) {
            int key = s_list[i];
            int j = i - 1;
            while (j >= 0 && s_list[j] > key) { s_list[j + 1] = s_list[j]; j--; }
            s_list[j + 1] = key;
        }
    }
    __syncthreads();

    float acc = 0.0f;
    int i = 0;
    for (; i + 4 <= n; i += 4) {    // MLP=4 on gathers, order preserved
        int u0 = s_list[i], u1 = s_list[i + 1], u2 = s_list[i + 2], u3 = s_list[i + 3];
        float v0 = g_neigh[(size_t)u0 * ND + t];
        float v1 = g_neigh[(size_t)u1 * ND + t];
        float v2 = g_neigh[(size_t)u2 * ND + t];
        float v3 = g_neigh[(size_t)u3 * ND + t];
        acc = (((acc + v0) + v1) + v2) + v3;
    }
    for (; i < n; i++) acc += g_neigh[(size_t)s_list[i] * ND + t];

    float norm = 1.0f / ((float)cnt + 1e-10f);
    g_A[(size_t)b * KTOT + r * ND + t] = acc * norm;
}

// ---------------- K3: split-K GEMM, f32x2, 16x8 per-thread tile ----------------
__device__ __forceinline__ unsigned long long pack2(float lo, float hi) {
    unsigned long long v;
    asm("mov.b64 %0, {%1, %2};" : "=l"(v) : "r"(__float_as_uint(lo)), "r"(__float_as_uint(hi)));
    return v;
}
__device__ __forceinline__ void unpack2(unsigned long long v, float& lo, float& hi) {
    unsigned int a, b;
    asm("mov.b64 {%0, %1}, %2;" : "=r"(a), "=r"(b) : "l"(v));
    lo = __uint_as_float(a); hi = __uint_as_float(b);
}
__device__ __forceinline__ unsigned long long fma2(unsigned long long a,
                                                   unsigned long long b,
                                                   unsigned long long c) {
    unsigned long long d;
    asm("fma.rn.f32x2 %0, %1, %2, %3;" : "=l"(d) : "l"(a), "l"(b), "l"(c));
    return d;
}

// 128 threads. Thread tile: Tm=16 (8 m-pairs), Tn=8 (two float4 n-groups at
// tn*4 and 64+tn*4). Block tile 128x128. A in smem transposed [k][m] so m-pairs
// load as ulonglong2 (no packs). grid = (16, 2, SPLIT).
__global__ __launch_bounds__(128) void gemm_splitk_kernel() {
    __shared__ float As[BKK][132];   // [k][m], stride 132 (16B-aligned rows)
    __shared__ float Bs[BKK][BN];    // [k][n]

    int tid = threadIdx.x;
    int m0 = blockIdx.x * BM;
    int n0 = blockIdx.y * BN;
    int kb = blockIdx.z * KSPL;
    int tn = tid & 15;               // n-group id (0..15)
    int tmi = tid >> 4;              // 0..7
    int tm = tmi * 16;

    const float* aBase = g_A + (size_t)m0 * KTOT + kb;
    const float* bBase = g_W + (size_t)kb * ND + n0;

    // staging: 4 float4 each for A and B per iter
    float4 aR[4], bR[4];
#pragma unroll
    for (int p = 0; p < 4; p++) {
        int f = tid + p * 128;
        aR[p] = *(const float4*)(aBase + (size_t)(f >> 2) * KTOT + (f & 3) * 4);
        bR[p] = *(const float4*)(bBase + (size_t)(f >> 5) * ND + (f & 31) * 4);
    }

    unsigned long long acc[8][8];
#pragma unroll
    for (int i = 0; i < 8; i++)
#pragma unroll
        for (int j = 0; j < 8; j++) acc[i][j] = 0ULL;

    for (int it = 0; it < ITERS; it++) {
        // commit staged tiles to smem (A transposed)
#pragma unroll
        for (int p = 0; p < 4; p++) {
            int f = tid + p * 128;
            int row = f >> 2, c4 = (f & 3) * 4;
            As[c4 + 0][row] = aR[p].x;
            As[c4 + 1][row] = aR[p].y;
            As[c4 + 2][row] = aR[p].z;
            As[c4 + 3][row] = aR[p].w;
            *(float4*)&Bs[f >> 5][(f & 31) * 4] = bR[p];
        }
        __syncthreads();

        if (it + 1 < ITERS) {       // prefetch next tile
            int ko = (it + 1) * BKK;
#pragma unroll
            for (int p = 0; p < 4; p++) {
                int f = tid + p * 128;
                aR[p] = *(const float4*)(aBase + (size_t)(f >> 2) * KTOT + ko + (f & 3) * 4);
                bR[p] = *(const float4*)(bBase + (size_t)(ko + (f >> 5)) * ND + (f & 31) * 4);
            }
        }

#pragma unroll
        for (int k = 0; k < BKK; k++) {
            ulonglong2 a01 = *(const ulonglong2*)&As[k][tm];
            ulonglong2 a23 = *(const ulonglong2*)&As[k][tm + 4];
            ulonglong2 a45 = *(const ulonglong2*)&As[k][tm + 8];
            ulonglong2 a67 = *(const ulonglong2*)&As[k][tm + 12];
            float4 b0 = *(const float4*)&Bs[k][tn * 4];
            float4 b1 = *(const float4*)&Bs[k][64 + tn * 4];
            unsigned long long bb[8];
            bb[0] = pack2(b0.x, b0.x); bb[1] = pack2(b0.y, b0.y);
            bb[2] = pack2(b0.z, b0.z); bb[3] = pack2(b0.w, b0.w);
            bb[4] = pack2(b1.x, b1.x); bb[5] = pack2(b1.y, b1.y);
            bb[6] = pack2(b1.z, b1.z); bb[7] = pack2(b1.w, b1.w);
            unsigned long long ap[8] = {a01.x, a01.y, a23.x, a23.y,
                                        a45.x, a45.y, a67.x, a67.y};
#pragma unroll
            for (int mp = 0; mp < 8; mp++)
#pragma unroll
                for (int j = 0; j < 8; j++)
                    acc[mp][j] = fma2(ap[mp], bb[j], acc[mp][j]);
        }
        __syncthreads();
    }

    // write partials: per m-pair, 2 rows x 2 n-groups of float4
    float* pBase = g_part + (size_t)blockIdx.z * NB * ND;
#pragma unroll
    for (int mp = 0; mp < 8; mp++) {
        int m = m0 + tm + 2 * mp;
        float lo[8], hi[8];
#pragma unroll
        for (int j = 0; j < 8; j++) unpack2(acc[mp][j], lo[j], hi[j]);
        float4 r0a = {lo[0], lo[1], lo[2], lo[3]};
        float4 r0b = {lo[4], lo[5], lo[6], lo[7]};
        float4 r1a = {hi[0], hi[1], hi[2], hi[3]};
        float4 r1b = {hi[4], hi[5], hi[6], hi[7]};
        *(float4*)&pBase[(size_t)m * ND + n0 + tn * 4]            = r0a;
        *(float4*)&pBase[(size_t)m * ND + n0 + 64 + tn * 4]       = r0b;
        *(float4*)&pBase[(size_t)(m + 1) * ND + n0 + tn * 4]      = r1a;
        *(float4*)&pBase[(size_t)(m + 1) * ND + n0 + 64 + tn * 4] = r1b;
    }
}

// ---------------- K4: deterministic reduce + ReLU ----------------
__global__ void reduce_relu_kernel(float* __restrict__ out) {
    int idx = blockIdx.x * 256 + threadIdx.x;      // float4 index, 131072 total
    const float4* p = (const float4*)g_part;
    float4 s = p[idx];
#pragma unroll
    for (int sp = 1; sp < SPLIT; sp++) {
        float4 v = p[(size_t)sp * (NB * ND / 4) + idx];
        s.x += v.x; s.y += v.y; s.z += v.z; s.w += v.w;
    }
    s.x = s.x > 0.0f ? s.x : 0.0f;
    s.y = s.y > 0.0f ? s.y : 0.0f;
    s.z = s.z > 0.0f ? s.z : 0.0f;
    s.w = s.w > 0.0f ? s.w : 0.0f;
    ((float4*)out)[idx] = s;
}

// ---------------- launch ----------------
extern "C" void kernel_launch(void* const* d_in, const int* in_sizes, int n_in,
                              void* d_out, int out_size) {
    const int*   nodes  = nullptr;
    const int*   uniq   = nullptr;
    const float* masks  = nullptr;
    const float* emb    = nullptr;
    const float* weight = nullptr;
    const float* relw   = nullptr;

    for (int i = 0; i < n_in; i++) {
        switch (in_sizes[i]) {
            case NB:           nodes  = (const int*)d_in[i];   break;
            case NU:           uniq   = (const int*)d_in[i];   break;
            case NR * NB * NU: masks  = (const float*)d_in[i]; break;
            case 100000 * ND:  emb    = (const float*)d_in[i]; break;
            case ND * ND:      weight = (const float*)d_in[i]; break;
            case NR * ND * ND: relw   = (const float*)d_in[i]; break;
            default: break;
        }
    }
    float* out = (float*)d_out;

    build_w_kernel<<<KTOT, 256>>>(weight, relw);
    gather_kernel<<<NU + NB, 256>>>(emb, uniq, nodes);
    mask_agg_kernel<<<NR * NB, 256>>>(masks);
    dim3 g3(NB / BM, ND / BN, SPLIT);
    gemm_splitk_kernel<<<g3, 128>>>();
    reduce_relu_kernel<<<NB * ND / 4 / 256, 256>>>(out);
}

// round 3
// speedup vs baseline: 1.5775x; 1.1175x over previous
#include <cuda_runtime.h>
#include <cstdint>

#define NB   2048      // batch B
#define NU   8192      // unique U
#define ND   256       // dim D
#define NR   8         // relations R
#define KTOT (NR*ND + ND)   // 2304 combined GEMM K

// ---------------- scratch (no allocations allowed) ----------------
__device__ __align__(16) float g_neigh[NU * ND];         // 8 MB
__device__ __align__(16) float g_A[(size_t)NB * KTOT];   // 18.9 MB
__device__ __align__(16) float g_W[KTOT * ND];           // 2.36 MB

#define SPLIT 9
#define KSPL  (KTOT / SPLIT)   // 256
#define BKK   16
#define ITERS (KSPL / BKK)     // 16
#define BM    128
#define BN    128

__device__ __align__(16) float g_part[(size_t)SPLIT * NB * ND]; // 18 MB

// ---------------- K1a: build combined weight matrix ----------------
__global__ void build_w_kernel(const float* __restrict__ weight,
                               const float* __restrict__ relw) {
    int k = blockIdx.x;
    int o = threadIdx.x;
    float v;
    if (k < NR * ND) {
        int r = k >> 8;
        int d = k & 255;
        v = relw[((size_t)r * ND + o) * ND + d];
    } else {
        int d = k - NR * ND;
        v = weight[o * ND + d];
    }
    g_W[(size_t)k * ND + o] = v;
}

// ---------------- K1b: gathers (float4, 4 rows per block) ----------------
__global__ void gather_kernel(const float* __restrict__ emb,
                              const int* __restrict__ unique_idx,
                              const int* __restrict__ nodes) {
    int blk = blockIdx.x;
    int t = threadIdx.x;
    int rowInBlk = t >> 6;           // 0..3
    int c = t & 63;                  // float4 column 0..63
    const float4* emb4 = (const float4*)emb;
    if (blk < NU / 4) {
        int u = blk * 4 + rowInBlk;
        int src = unique_idx[u];
        ((float4*)g_neigh)[(size_t)u * 64 + c] = emb4[(size_t)src * 64 + c];
    } else {
        int b = (blk - NU / 4) * 4 + rowInBlk;
        int src = nodes[b];
        *(float4*)&g_A[(size_t)b * KTOT + NR * ND + c * 4] = emb4[(size_t)src * 64 + c];
    }
}

// ---------------- K2: mask scan + sparse mean aggregation ----------------
#define LIST_CAP 256
__global__ void mask_agg_kernel(const float* __restrict__ masks) {
    __shared__ int s_list[LIST_CAP];
    __shared__ int s_cnt;
    int t = threadIdx.x;            // 256 threads, t == output dim d
    int rb = blockIdx.x;            // rb = r*2048 + b
    int r = rb >> 11;
    int b = rb & 2047;

    if (t == 0) s_cnt = 0;
    __syncthreads();

    const float4* row = (const float4*)(masks + (size_t)rb * NU);
#pragma unroll
    for (int c = 0; c < 8; c++) {
        int f4 = c * 256 + t;
        float4 v = __ldcs(&row[f4]);   // streaming: don't pollute L2
        int base = f4 * 4;
        if (v.x != 0.0f) { int p = atomicAdd(&s_cnt, 1); if (p < LIST_CAP) s_list[p] = base; }
        if (v.y != 0.0f) { int p = atomicAdd(&s_cnt, 1); if (p < LIST_CAP) s_list[p] = base + 1; }
        if (v.z != 0.0f) { int p = atomicAdd(&s_cnt, 1); if (p < LIST_CAP) s_list[p] = base + 2; }
        if (v.w != 0.0f) { int p = atomicAdd(&s_cnt, 1); if (p < LIST_CAP) s_list[p] = base + 3; }
    }
    __syncthreads();

    int cnt = s_cnt;
    int n = cnt < LIST_CAP ? cnt : LIST_CAP;

    if (t == 0 && n > 1) {   // deterministic accumulation order
        for (int i = 1; i < n; i++) {
            int key = s_list[i];
            int j = i - 1;
            while (j >= 0 && s_list[j] > key) { s_list[j + 1] = s_list[j]; j--; }
            s_list[j + 1] = key;
        }
    }
    __syncthreads();

    float acc = 0.0f;
    int i = 0;
    for (; i + 4 <= n; i += 4) {    // MLP=4, left-to-right order preserved
        int u0 = s_list[i], u1 = s_list[i + 1], u2 = s_list[i + 2], u3 = s_list[i + 3];
        float v0 = g_neigh[(size_t)u0 * ND + t];
        float v1 = g_neigh[(size_t)u1 * ND + t];
        float v2 = g_neigh[(size_t)u2 * ND + t];
        float v3 = g_neigh[(size_t)u3 * ND + t];
        acc = (((acc + v0) + v1) + v2) + v3;
    }
    for (; i < n; i++) acc += g_neigh[(size_t)s_list[i] * ND + t];

    float norm = 1.0f / ((float)cnt + 1e-10f);
    g_A[(size_t)b * KTOT + r * ND + t] = acc * norm;
}

// ---------------- K3: split-K GEMM, f32x2, double-buffered smem ----------------
__device__ __forceinline__ unsigned long long pack2(float lo, float hi) {
    unsigned long long v;
    asm("mov.b64 %0, {%1, %2};" : "=l"(v) : "r"(__float_as_uint(lo)), "r"(__float_as_uint(hi)));
    return v;
}
__device__ __forceinline__ void unpack2(unsigned long long v, float& lo, float& hi) {
    unsigned int a, b;
    asm("mov.b64 {%0, %1}, %2;" : "=r"(a), "=r"(b) : "l"(v));
    lo = __uint_as_float(a); hi = __uint_as_float(b);
}
__device__ __forceinline__ unsigned long long fma2(unsigned long long a,
                                                   unsigned long long b,
                                                   unsigned long long c) {
    unsigned long long d;
    asm("fma.rn.f32x2 %0, %1, %2, %3;" : "=l"(d) : "l"(a), "l"(b), "l"(c));
    return d;
}

// 128 threads. Thread tile 16x8. Block tile 128x128x16, double-buffered smem,
// one __syncthreads per k-tile. grid = (16, 2, SPLIT).
__global__ __launch_bounds__(128) void gemm_splitk_kernel() {
    __shared__ float As[2][BKK][132];   // [buf][k][m]
    __shared__ float Bs[2][BKK][BN];    // [buf][k][n]

    int tid = threadIdx.x;
    int m0 = blockIdx.x * BM;
    int n0 = blockIdx.y * BN;
    int kb = blockIdx.z * KSPL;
    int tn = tid & 15;               // n-group id (0..15)
    int tm = (tid >> 4) * 16;        // m base (0..112)

    const float* aBase = g_A + (size_t)m0 * KTOT + kb;
    const float* bBase = g_W + (size_t)kb * ND + n0;

    // per-thread staging coords
    int fA[4], fB[4];
#pragma unroll
    for (int p = 0; p < 4; p++) { fA[p] = tid + p * 128; fB[p] = tid + p * 128; }

    float4 aR[4], bR[4];
#pragma unroll
    for (int p = 0; p < 4; p++) {
        int f = fA[p];
        aR[p] = *(const float4*)(aBase + (size_t)(f >> 2) * KTOT + (f & 3) * 4);
        bR[p] = *(const float4*)(bBase + (size_t)(f >> 5) * ND + (f & 31) * 4);
    }
    // commit tile 0 to buffer 0
#pragma unroll
    for (int p = 0; p < 4; p++) {
        int f = fA[p];
        int row = f >> 2, c4 = (f & 3) * 4;
        As[0][c4 + 0][row] = aR[p].x;
        As[0][c4 + 1][row] = aR[p].y;
        As[0][c4 + 2][row] = aR[p].z;
        As[0][c4 + 3][row] = aR[p].w;
        *(float4*)&Bs[0][f >> 5][(f & 31) * 4] = bR[p];
    }
    __syncthreads();

    unsigned long long acc[8][8];
#pragma unroll
    for (int i = 0; i < 8; i++)
#pragma unroll
        for (int j = 0; j < 8; j++) acc[i][j] = 0ULL;

    for (int it = 0; it < ITERS; it++) {
        int cur = it & 1;
        int nxt = cur ^ 1;

        if (it + 1 < ITERS) {        // issue global loads before compute
            int ko = (it + 1) * BKK;
#pragma unroll
            for (int p = 0; p < 4; p++) {
                int f = fA[p];
                aR[p] = *(const float4*)(aBase + (size_t)(f >> 2) * KTOT + ko + (f & 3) * 4);
                bR[p] = *(const float4*)(bBase + (size_t)(ko + (f >> 5)) * ND + (f & 31) * 4);
            }
        }

#pragma unroll
        for (int k = 0; k < BKK; k++) {
            ulonglong2 a01 = *(const ulonglong2*)&As[cur][k][tm];
            ulonglong2 a23 = *(const ulonglong2*)&As[cur][k][tm + 4];
            ulonglong2 a45 = *(const ulonglong2*)&As[cur][k][tm + 8];
            ulonglong2 a67 = *(const ulonglong2*)&As[cur][k][tm + 12];
            float4 b0 = *(const float4*)&Bs[cur][k][tn * 4];
            float4 b1 = *(const float4*)&Bs[cur][k][64 + tn * 4];
            unsigned long long bb[8];
            bb[0] = pack2(b0.x, b0.x); bb[1] = pack2(b0.y, b0.y);
            bb[2] = pack2(b0.z, b0.z); bb[3] = pack2(b0.w, b0.w);
            bb[4] = pack2(b1.x, b1.x); bb[5] = pack2(b1.y, b1.y);
            bb[6] = pack2(b1.z, b1.z); bb[7] = pack2(b1.w, b1.w);
            unsigned long long ap[8] = {a01.x, a01.y, a23.x, a23.y,
                                        a45.x, a45.y, a67.x, a67.y};
#pragma unroll
            for (int mp = 0; mp < 8; mp++)
#pragma unroll
                for (int j = 0; j < 8; j++)
                    acc[mp][j] = fma2(ap[mp], bb[j], acc[mp][j]);
        }

        if (it + 1 < ITERS) {        // commit next tile to other buffer
#pragma unroll
            for (int p = 0; p < 4; p++) {
                int f = fA[p];
                int row = f >> 2, c4 = (f & 3) * 4;
                As[nxt][c4 + 0][row] = aR[p].x;
                As[nxt][c4 + 1][row] = aR[p].y;
                As[nxt][c4 + 2][row] = aR[p].z;
                As[nxt][c4 + 3][row] = aR[p].w;
                *(float4*)&Bs[nxt][f >> 5][(f & 31) * 4] = bR[p];
            }
        }
        __syncthreads();
    }

    // write partials
    float* pBase = g_part + (size_t)blockIdx.z * NB * ND;
#pragma unroll
    for (int mp = 0; mp < 8; mp++) {
        int m = m0 + tm + 2 * mp;
        float lo[8], hi[8];
#pragma unroll
        for (int j = 0; j < 8; j++) unpack2(acc[mp][j], lo[j], hi[j]);
        float4 r0a = {lo[0], lo[1], lo[2], lo[3]};
        float4 r0b = {lo[4], lo[5], lo[6], lo[7]};
        float4 r1a = {hi[0], hi[1], hi[2], hi[3]};
        float4 r1b = {hi[4], hi[5], hi[6], hi[7]};
        *(float4*)&pBase[(size_t)m * ND + n0 + tn * 4]            = r0a;
        *(float4*)&pBase[(size_t)m * ND + n0 + 64 + tn * 4]       = r0b;
        *(float4*)&pBase[(size_t)(m + 1) * ND + n0 + tn * 4]      = r1a;
        *(float4*)&pBase[(size_t)(m + 1) * ND + n0 + 64 + tn * 4] = r1b;
    }
}

// ---------------- K4: deterministic reduce + ReLU ----------------
__global__ void reduce_relu_kernel(float* __restrict__ out) {
    int idx = blockIdx.x * 256 + threadIdx.x;      // float4 index, 131072 total
    const float4* p = (const float4*)g_part;
    float4 s = p[idx];
#pragma unroll
    for (int sp = 1; sp < SPLIT; sp++) {
        float4 v = p[(size_t)sp * (NB * ND / 4) + idx];
        s.x += v.x; s.y += v.y; s.z += v.z; s.w += v.w;
    }
    s.x = s.x > 0.0f ? s.x : 0.0f;
    s.y = s.y > 0.0f ? s.y : 0.0f;
    s.z = s.z > 0.0f ? s.z : 0.0f;
    s.w = s.w > 0.0f ? s.w : 0.0f;
    ((float4*)out)[idx] = s;
}

// ---------------- launch ----------------
extern "C" void kernel_launch(void* const* d_in, const int* in_sizes, int n_in,
                              void* d_out, int out_size) {
    const int*   nodes  = nullptr;
    const int*   uniq   = nullptr;
    const float* masks  = nullptr;
    const float* emb    = nullptr;
    const float* weight = nullptr;
    const float* relw   = nullptr;

    for (int i = 0; i < n_in; i++) {
        switch (in_sizes[i]) {
            case NB:           nodes  = (const int*)d_in[i];   break;
            case NU:           uniq   = (const int*)d_in[i];   break;
            case NR * NB * NU: masks  = (const float*)d_in[i]; break;
            case 100000 * ND:  emb    = (const float*)d_in[i]; break;
            case ND * ND:      weight = (const float*)d_in[i]; break;
            case NR * ND * ND: relw   = (const float*)d_in[i]; break;
            default: break;
        }
    }
    float* out = (float*)d_out;

    build_w_kernel<<<KTOT, 256>>>(weight, relw);
    gather_kernel<<<NU / 4 + NB / 4, 256>>>(emb, uniq, nodes);
    mask_agg_kernel<<<NR * NB, 256>>>(masks);
    dim3 g3(NB / BM, ND / BN, SPLIT);
    gemm_splitk_kernel<<<g3, 128>>>();
    reduce_relu_kernel<<<NB * ND / 4 / 256, 256>>>(out);
}

// round 5
// speedup vs baseline: 1.7917x; 1.1358x over previous
#include <cuda_runtime.h>
#include <cuda_bf16.h>
#include <cstdint>

#define NB   2048
#define NU   8192
#define ND   256
#define NR   8
#define KTOT (NR*ND + ND)   // 2304

// ---------------- scratch ----------------
__device__ __align__(16) float         g_neigh[NU * ND];
__device__ __align__(16) __nv_bfloat16 g_Ah[(size_t)NB * KTOT];
__device__ __align__(16) __nv_bfloat16 g_Al[(size_t)NB * KTOT];
__device__ __align__(16) __nv_bfloat16 g_Bh[(size_t)ND * KTOT];   // B[n][k] = W[k][n]
__device__ __align__(16) __nv_bfloat16 g_Bl[(size_t)ND * KTOT];

#define GSPLIT 6
#define GKSPL  (KTOT / GSPLIT)   // 384
#define GCHUNK 32
#define GITERS (GKSPL / GCHUNK)  // 12
__device__ __align__(16) float g_part[(size_t)GSPLIT * NB * ND];

// ---------------- helpers ----------------
__device__ __forceinline__ uint32_t smem_u32(const void* p) {
    uint32_t a;
    asm("{ .reg .u64 t; cvta.to.shared.u64 t, %1; cvt.u32.u64 %0, t; }" : "=r"(a) : "l"(p));
    return a;
}
__device__ __forceinline__ void cp16(uint32_t dst, const void* src) {
    asm volatile("cp.async.ca.shared.global [%0], [%1], 16;" :: "r"(dst), "l"(src) : "memory");
}
__device__ __forceinline__ void cp_commit() {
    asm volatile("cp.async.commit_group;" ::: "memory");
}
__device__ __forceinline__ void cp_wait1() {
    asm volatile("cp.async.wait_group 1;" ::: "memory");
}
__device__ __forceinline__ void cp_wait0() {
    asm volatile("cp.async.wait_group 0;" ::: "memory");
}
__device__ __forceinline__ void ldm4(uint32_t* r, uint32_t addr) {
    asm volatile("ldmatrix.sync.aligned.m8n8.x4.shared.b16 {%0,%1,%2,%3}, [%4];"
        : "=r"(r[0]), "=r"(r[1]), "=r"(r[2]), "=r"(r[3]) : "r"(addr));
}
__device__ __forceinline__ void mma16816(float* d, const uint32_t* a, const uint32_t* b) {
    asm volatile("mma.sync.aligned.m16n8k16.row.col.f32.bf16.bf16.f32 "
        "{%0,%1,%2,%3}, {%4,%5,%6,%7}, {%8,%9}, {%0,%1,%2,%3};"
        : "+f"(d[0]), "+f"(d[1]), "+f"(d[2]), "+f"(d[3])
        : "r"(a[0]), "r"(a[1]), "r"(a[2]), "r"(a[3]), "r"(b[0]), "r"(b[1]));
}
__device__ __forceinline__ void bf16_split(float v, __nv_bfloat16& h, __nv_bfloat16& l) {
    h = __float2bfloat16(v);
    l = __float2bfloat16(v - __bfloat162float(h));
}

// ---------------- K1a: build B = W^T (bf16 hi/lo) ----------------
__global__ void build_w_kernel(const float* __restrict__ weight,
                               const float* __restrict__ relw) {
    int n = blockIdx.x;
    int t = threadIdx.x;
#pragma unroll
    for (int j = 0; j < 9; j++) {
        int k = j * 256 + t;
        float v;
        if (k < NR * ND) {
            int r = k >> 8, d = k & 255;
            v = relw[((size_t)r * ND + n) * ND + d];
        } else {
            v = weight[n * ND + (k - NR * ND)];
        }
        __nv_bfloat16 h, l;
        bf16_split(v, h, l);
        g_Bh[(size_t)n * KTOT + k] = h;
        g_Bl[(size_t)n * KTOT + k] = l;
    }
}

// ---------------- K1b: gathers ----------------
__global__ void gather_kernel(const float* __restrict__ emb,
                              const int* __restrict__ unique_idx,
                              const int* __restrict__ nodes) {
    int blk = blockIdx.x;
    int t = threadIdx.x;
    int rowInBlk = t >> 6;
    int c = t & 63;
    const float4* emb4 = (const float4*)emb;
    if (blk < NU / 4) {
        int u = blk * 4 + rowInBlk;
        int src = unique_idx[u];
        ((float4*)g_neigh)[(size_t)u * 64 + c] = emb4[(size_t)src * 64 + c];
    } else {
        int b = (blk - NU / 4) * 4 + rowInBlk;
        int src = nodes[b];
        float4 v = emb4[(size_t)src * 64 + c];
        size_t base = (size_t)b * KTOT + NR * ND + c * 4;
        __nv_bfloat16 h, l;
        bf16_split(v.x, h, l); g_Ah[base + 0] = h; g_Al[base + 0] = l;
        bf16_split(v.y, h, l); g_Ah[base + 1] = h; g_Al[base + 1] = l;
        bf16_split(v.z, h, l); g_Ah[base + 2] = h; g_Al[base + 2] = l;
        bf16_split(v.w, h, l); g_Ah[base + 3] = h; g_Al[base + 3] = l;
    }
}

// ---------------- K2: mask scan + sparse mean aggregation ----------------
#define LIST_CAP 256
__global__ void mask_agg_kernel(const float* __restrict__ masks) {
    __shared__ int s_list[LIST_CAP];
    __shared__ int s_cnt;
    int t = threadIdx.x;
    int rb = blockIdx.x;
    int r = rb >> 11;
    int b = rb & 2047;

    if (t == 0) s_cnt = 0;
    __syncthreads();

    const float4* row = (const float4*)(masks + (size_t)rb * NU);
#pragma unroll
    for (int c = 0; c < 8; c++) {
        int f4 = c * 256 + t;
        float4 v = __ldcs(&row[f4]);
        int base = f4 * 4;
        if (v.x != 0.0f) { int p = atomicAdd(&s_cnt, 1); if (p < LIST_CAP) s_list[p] = base; }
        if (v.y != 0.0f) { int p = atomicAdd(&s_cnt, 1); if (p < LIST_CAP) s_list[p] = base + 1; }
        if (v.z != 0.0f) { int p = atomicAdd(&s_cnt, 1); if (p < LIST_CAP) s_list[p] = base + 2; }
        if (v.w != 0.0f) { int p = atomicAdd(&s_cnt, 1); if (p < LIST_CAP) s_list[p] = base + 3; }
    }
    __syncthreads();

    int cnt = s_cnt;
    int n = cnt < LIST_CAP ? cnt : LIST_CAP;

    if (t == 0 && n > 1) {
        for (int i = 1; i < n; i++) {
            int key = s_list[i];
            int j = i - 1;
            while (j >= 0 && s_list[j] > key) { s_list[j + 1] = s_list[j]; j--; }
            s_list[j + 1] = key;
        }
    }
    __syncthreads();

    float acc = 0.0f;
    int i = 0;
    for (; i + 4 <= n; i += 4) {
        int u0 = s_list[i], u1 = s_list[i + 1], u2 = s_list[i + 2], u3 = s_list[i + 3];
        float v0 = g_neigh[(size_t)u0 * ND + t];
        float v1 = g_neigh[(size_t)u1 * ND + t];
        float v2 = g_neigh[(size_t)u2 * ND + t];
        float v3 = g_neigh[(size_t)u3 * ND + t];
        acc = (((acc + v0) + v1) + v2) + v3;
    }
    for (; i < n; i++) acc += g_neigh[(size_t)s_list[i] * ND + t];

    float v = acc * (1.0f / ((float)cnt + 1e-10f));
    __nv_bfloat16 h, l;
    bf16_split(v, h, l);
    g_Ah[(size_t)b * KTOT + r * ND + t] = h;
    g_Al[(size_t)b * KTOT + r * ND + t] = l;
}

// ---------------- K3: mma.sync bf16 2-term-split GEMM ----------------
// Block 128(m) x 64(n), 4 warps (2x2), warp tile 64x32, k-chunk 32,
// cp.async double-buffered. grid (16, 4, GSPLIT).
// SMEM buffer layout (bytes, padded rows of 40 bf16 = 80B):
//   AH: 128*80 = 10240 | AL: 10240 | BH: 64*80 = 5120 | BL: 5120  => 30720/buf
#define SM_AH 0
#define SM_AL 10240
#define SM_BH 20480
#define SM_BL 25600
#define SM_BUF 30720
#define GSMEM (2 * SM_BUF)

__device__ __forceinline__ void load_chunk(uint32_t sbuf, int m0, int n0, int kc, int tid) {
    // A: 1024 cp16 ops (2 src * 128 rows * 4)
#pragma unroll
    for (int p = 0; p < 8; p++) {
        int o = tid + p * 128;
        int src = o >> 9;
        int rem = o & 511;
        int row = rem >> 2;
        int c16 = rem & 3;
        const __nv_bfloat16* g = (src ? g_Al : g_Ah) + (size_t)(m0 + row) * KTOT + kc + c16 * 8;
        cp16(sbuf + (src ? SM_AL : SM_AH) + row * 80 + c16 * 16, g);
    }
    // B: 512 cp16 ops (2 src * 64 rows * 4)
#pragma unroll
    for (int p = 0; p < 4; p++) {
        int o = tid + p * 128;
        int src = o >> 8;
        int rem = o & 255;
        int row = rem >> 2;
        int c16 = rem & 3;
        const __nv_bfloat16* g = (src ? g_Bl : g_Bh) + (size_t)(n0 + row) * KTOT + kc + c16 * 8;
        cp16(sbuf + (src ? SM_BL : SM_BH) + row * 80 + c16 * 16, g);
    }
}

__global__ __launch_bounds__(128) void gemm_mma_kernel() {
    extern __shared__ char smem[];
    uint32_t sb = smem_u32(smem);
    int tid = threadIdx.x;
    int lane = tid & 31;
    int wid = tid >> 5;
    int wm = wid >> 1;          // 0..1
    int wn = wid & 1;           // 0..1
    int m0 = blockIdx.x * 128;
    int n0 = blockIdx.y * 64;
    int sp = blockIdx.z;
    int kb = sp * GKSPL;

    float acc[4][4][4];
#pragma unroll
    for (int mi = 0; mi < 4; mi++)
#pragma unroll
        for (int nj = 0; nj < 4; nj++)
#pragma unroll
            for (int q = 0; q < 4; q++) acc[mi][nj][q] = 0.0f;

    load_chunk(sb, m0, n0, kb, tid);
    cp_commit();

    int lr = lane & 15;
    int lch = (lane >> 4) * 8;

    for (int it = 0; it < GITERS; it++) {
        uint32_t cbuf = sb + (it & 1) * SM_BUF;
        if (it + 1 < GITERS) {
            load_chunk(sb + ((it + 1) & 1) * SM_BUF, m0, n0, kb + (it + 1) * GCHUNK, tid);
            cp_commit();
            cp_wait1();
        } else {
            cp_wait0();
        }
        __syncthreads();

#pragma unroll
        for (int s = 0; s < 2; s++) {
            uint32_t ah[4][4], al[4][4], bh[4][2], bl[4][2];
#pragma unroll
            for (int mi = 0; mi < 4; mi++) {
                uint32_t off = (uint32_t)(wm * 64 + mi * 16 + lr) * 80 + (s * 16 + lch) * 2;
                ldm4(ah[mi], cbuf + SM_AH + off);
                ldm4(al[mi], cbuf + SM_AL + off);
            }
#pragma unroll
            for (int p = 0; p < 2; p++) {
                uint32_t off = (uint32_t)(wn * 32 + p * 16 + lr) * 80 + (s * 16 + lch) * 2;
                uint32_t r[4];
                ldm4(r, cbuf + SM_BH + off);
                bh[2 * p][0] = r[0]; bh[2 * p][1] = r[2];
                bh[2 * p + 1][0] = r[1]; bh[2 * p + 1][1] = r[3];
                ldm4(r, cbuf + SM_BL + off);
                bl[2 * p][0] = r[0]; bl[2 * p][1] = r[2];
                bl[2 * p + 1][0] = r[1]; bl[2 * p + 1][1] = r[3];
            }
#pragma unroll
            for (int mi = 0; mi < 4; mi++)
#pragma unroll
                for (int nj = 0; nj < 4; nj++)
                    mma16816(acc[mi][nj], ah[mi], bh[nj]);
#pragma unroll
            for (int mi = 0; mi < 4; mi++)
#pragma unroll
                for (int nj = 0; nj < 4; nj++)
                    mma16816(acc[mi][nj], ah[mi], bl[nj]);
#pragma unroll
            for (int mi = 0; mi < 4; mi++)
#pragma unroll
                for (int nj = 0; nj < 4; nj++)
                    mma16816(acc[mi][nj], al[mi], bh[nj]);
        }
        __syncthreads();
    }

    // epilogue -> g_part[sp]
    float* pB = g_part + (size_t)sp * NB * ND;
    int g = lane >> 2;
    int tq = lane & 3;
#pragma unroll
    for (int mi = 0; mi < 4; mi++) {
#pragma unroll
        for (int nj = 0; nj < 4; nj++) {
            int m = m0 + wm * 64 + mi * 16 + g;
            int n = n0 + wn * 32 + nj * 8 + tq * 2;
            float2 v0 = {acc[mi][nj][0], acc[mi][nj][1]};
            float2 v1 = {acc[mi][nj][2], acc[mi][nj][3]};
            *(float2*)&pB[(size_t)m * ND + n] = v0;
            *(float2*)&pB[(size_t)(m + 8) * ND + n] = v1;
        }
    }
}

// ---------------- K4: deterministic reduce + ReLU ----------------
__global__ void reduce_relu_kernel(float* __restrict__ out) {
    int idx = blockIdx.x * 256 + threadIdx.x;
    const float4* p = (const float4*)g_part;
    float4 s = p[idx];
#pragma unroll
    for (int sp = 1; sp < GSPLIT; sp++) {
        float4 v = p[(size_t)sp * (NB * ND / 4) + idx];
        s.x += v.x; s.y += v.y; s.z += v.z; s.w += v.w;
    }
    s.x = s.x > 0.0f ? s.x : 0.0f;
    s.y = s.y > 0.0f ? s.y : 0.0f;
    s.z = s.z > 0.0f ? s.z : 0.0f;
    s.w = s.w > 0.0f ? s.w : 0.0f;
    ((float4*)out)[idx] = s;
}

// ---------------- launch ----------------
extern "C" void kernel_launch(void* const* d_in, const int* in_sizes, int n_in,
                              void* d_out, int out_size) {
    const int*   nodes  = nullptr;
    const int*   uniq   = nullptr;
    const float* masks  = nullptr;
    const float* emb    = nullptr;
    const float* weight = nullptr;
    const float* relw   = nullptr;

    for (int i = 0; i < n_in; i++) {
        switch (in_sizes[i]) {
            case NB:           nodes  = (const int*)d_in[i];   break;
            case NU:           uniq   = (const int*)d_in[i];   break;
            case NR * NB * NU: masks  = (const float*)d_in[i]; break;
            case 100000 * ND:  emb    = (const float*)d_in[i]; break;
            case ND * ND:      weight = (const float*)d_in[i]; break;
            case NR * ND * ND: relw   = (const float*)d_in[i]; break;
            default: break;
        }
    }
    float* out = (float*)d_out;

    static int smem_set = 0;
    if (!smem_set) {
        cudaFuncSetAttribute(gemm_mma_kernel, cudaFuncAttributeMaxDynamicSharedMemorySize, GSMEM);
        smem_set = 1;
    }

    build_w_kernel<<<ND, 256>>>(weight, relw);
    gather_kernel<<<NU / 4 + NB / 4, 256>>>(emb, uniq, nodes);
    mask_agg_kernel<<<NR * NB, 256>>>(masks);
    dim3 g3(NB / 128, ND / 64, GSPLIT);
    gemm_mma_kernel<<<g3, 128, GSMEM>>>();
    reduce_relu_kernel<<<NB * ND / 4 / 256, 256>>>(out);
}